// round 1
// baseline (speedup 1.0000x reference)
#include <cuda_runtime.h>
#include <math.h>

#define BB    256
#define DIN   2048
#define HID   2048
#define NSEG  10
#define DCTX  1024
#define NOUT  100
#define TOPK  102

// Scratch (static device allocations are allowed)
__device__ float g_y[BB * HID];
__device__ float g_gate[BB * HID];
__device__ float g_h[BB * HID];

// ---------------------------------------------------------------------------
// FF GEMM: Y[m,n] = sum_k X[m,k] * W[n,k] * Mk[n,k] + bias[n]
// M=256, N=2048, K passed (2048). Tiles: 64x64x16, 256 threads, 4x4 microtile.
// ---------------------------------------------------------------------------
__global__ __launch_bounds__(256) void ff_kernel(
    const float* __restrict__ X, const float* __restrict__ W,
    const float* __restrict__ Mk, const float* __restrict__ bias,
    float* __restrict__ Y, int K)
{
    __shared__ float As[16][68];   // As[kk][m]
    __shared__ float Bs[16][68];   // Bs[kk][n]
    int tid = threadIdx.x;
    int tx = tid & 15, ty = tid >> 4;
    int lk = tid & 15, lr = tid >> 4;
    int n0 = blockIdx.x * 64, m0 = blockIdx.y * 64;
    float acc[4][4] = {};
    for (int k0 = 0; k0 < K; k0 += 16) {
        #pragma unroll
        for (int p = 0; p < 4; p++) {
            int r = p * 16 + lr;
            As[lk][r] = X[(size_t)(m0 + r) * K + k0 + lk];
            size_t off = (size_t)(n0 + r) * K + k0 + lk;
            Bs[lk][r] = W[off] * Mk[off];
        }
        __syncthreads();
        #pragma unroll
        for (int kk = 0; kk < 16; kk++) {
            float4 a = *(const float4*)&As[kk][ty * 4];
            float4 b = *(const float4*)&Bs[kk][tx * 4];
            float av[4] = {a.x, a.y, a.z, a.w};
            float bv[4] = {b.x, b.y, b.z, b.w};
            #pragma unroll
            for (int i = 0; i < 4; i++)
                #pragma unroll
                for (int j = 0; j < 4; j++)
                    acc[i][j] += av[i] * bv[j];
        }
        __syncthreads();
    }
    #pragma unroll
    for (int i = 0; i < 4; i++) {
        int m = m0 + ty * 4 + i;
        #pragma unroll
        for (int j = 0; j < 4; j++) {
            int n = n0 + tx * 4 + j;
            Y[(size_t)m * HID + n] = acc[i][j] + bias[n];
        }
    }
}

// ---------------------------------------------------------------------------
// Dendrite + gating: d[b,u,s] = sum_c ctx[b,c]*segW[u,s,c]*maskS[u,s,c]
// gate[b,u] = sigmoid(d[b,u,argmax_s |d|]) (first-index tie-break like argmax)
// Block tile: 64 batch rows x 16 units (x all 10 segments). 256 threads,
// each thread: 4 batch rows x 1 unit x 10 segments = 40 accumulators.
// ---------------------------------------------------------------------------
__global__ __launch_bounds__(256) void dend_kernel(
    const float* __restrict__ ctx, const float* __restrict__ segW,
    const float* __restrict__ maskS, float* __restrict__ gate)
{
    __shared__ float Cs[16][68];        // Cs[kk][m]
    __shared__ float Ws[16][16][12];    // Ws[kk][u][s], s<10 valid, padded to 12
    int tid = threadIdx.x;
    int tx = tid & 15, ty = tid >> 4;
    int lk = tid & 15, lp = tid >> 4;
    int u0 = blockIdx.x * 16, m0 = blockIdx.y * 64;
    float acc[4][10] = {};
    for (int k0 = 0; k0 < DCTX; k0 += 16) {
        #pragma unroll
        for (int p = 0; p < 4; p++)
            Cs[lk][p * 16 + lp] = ctx[(size_t)(m0 + p * 16 + lp) * DCTX + k0 + lk];
        #pragma unroll
        for (int p = 0; p < 10; p++) {
            int idx = p * 16 + lp;           // 0..159
            int u = idx / 10, s = idx % 10;
            size_t off = ((size_t)(u0 + u) * NSEG + s) * DCTX + k0 + lk;
            Ws[lk][u][s] = segW[off] * maskS[off];
        }
        __syncthreads();
        #pragma unroll
        for (int kk = 0; kk < 16; kk++) {
            float4 c4 = *(const float4*)&Cs[kk][ty * 4];
            float4 w0 = *(const float4*)&Ws[kk][tx][0];
            float4 w1 = *(const float4*)&Ws[kk][tx][4];
            float4 w2 = *(const float4*)&Ws[kk][tx][8];
            float cv[4]  = {c4.x, c4.y, c4.z, c4.w};
            float wv[10] = {w0.x, w0.y, w0.z, w0.w,
                            w1.x, w1.y, w1.z, w1.w,
                            w2.x, w2.y};
            #pragma unroll
            for (int i = 0; i < 4; i++)
                #pragma unroll
                for (int s = 0; s < 10; s++)
                    acc[i][s] += cv[i] * wv[s];
        }
        __syncthreads();
    }
    #pragma unroll
    for (int i = 0; i < 4; i++) {
        float best = fabsf(acc[i][0]);
        float chosen = acc[i][0];
        #pragma unroll
        for (int s = 1; s < 10; s++) {
            float a = fabsf(acc[i][s]);
            if (a > best) { best = a; chosen = acc[i][s]; }
        }
        float gval = 1.f / (1.f + expf(-chosen));
        gate[(size_t)(m0 + ty * 4 + i) * HID + u0 + tx] = gval;
    }
}

// ---------------------------------------------------------------------------
// Gate multiply + k-winners (top 102 of 2048 per row; rest zeroed).
// One block per batch row, radix-select (4 x 8-bit passes, MSB first) on
// order-preserving uint keys.
// ---------------------------------------------------------------------------
__device__ __forceinline__ unsigned f2key(float f) {
    unsigned u = __float_as_uint(f);
    return (u & 0x80000000u) ? ~u : (u | 0x80000000u);
}

__global__ __launch_bounds__(256) void gate_topk_kernel(
    const float* __restrict__ Y, const float* __restrict__ G,
    float* __restrict__ H)
{
    __shared__ float    vals[HID];
    __shared__ unsigned keys[HID];
    __shared__ int      hist[256];
    __shared__ int      s_digit, s_rem, eqctr;
    int b = blockIdx.x;
    int t = threadIdx.x;
    const float* yr = Y + (size_t)b * HID;
    const float* gr = G + (size_t)b * HID;
    #pragma unroll
    for (int i = 0; i < HID / 256; i++) {
        int j = t + 256 * i;
        float v = yr[j] * gr[j];
        vals[j] = v;
        keys[j] = f2key(v);
    }
    __syncthreads();

    unsigned prefix = 0, pmask = 0;
    int remaining = TOPK;
    for (int pass = 0; pass < 4; pass++) {
        int shift = 24 - 8 * pass;
        hist[t] = 0;
        __syncthreads();
        #pragma unroll
        for (int i = 0; i < HID / 256; i++) {
            unsigned k = keys[t + 256 * i];
            if ((k & pmask) == prefix)
                atomicAdd(&hist[(k >> shift) & 255], 1);
        }
        __syncthreads();
        if (t == 0) {
            int cum = 0;
            for (int d = 255; d >= 0; d--) {
                int c = hist[d];
                if (cum + c >= remaining) { s_digit = d; s_rem = remaining - cum; break; }
                cum += c;
            }
        }
        __syncthreads();
        prefix |= ((unsigned)s_digit) << shift;
        pmask  |= 0xFFu << shift;
        remaining = s_rem;
        __syncthreads();
    }

    if (t == 0) eqctr = 0;
    __syncthreads();
    unsigned T = prefix;
    int need = remaining;
    #pragma unroll
    for (int i = 0; i < HID / 256; i++) {
        int j = t + 256 * i;
        unsigned k = keys[j];
        float o = 0.f;
        if (k > T) o = vals[j];
        else if (k == T) {
            int slot = atomicAdd(&eqctr, 1);
            if (slot < need) o = vals[j];
        }
        H[(size_t)b * HID + j] = o;
    }
}

// ---------------------------------------------------------------------------
// Dale output head: out[b,o] = sum_u h[b,u]*Wex[o,u] - Wei[o]*(h.Wix) + b_out[o]
// 4 batch rows per block, 128 threads (thread o < 100 computes one output col).
// ---------------------------------------------------------------------------
__global__ __launch_bounds__(128) void head_kernel(
    const float* __restrict__ Hm, const float* __restrict__ Wex,
    const float* __restrict__ Wix, const float* __restrict__ Wei,
    const float* __restrict__ bout, float* __restrict__ out)
{
    __shared__ float hrow[4][HID];
    __shared__ float red[4][128];
    int b0 = blockIdx.x * 4;
    int t = threadIdx.x;
    float pr[4] = {0.f, 0.f, 0.f, 0.f};
    for (int r = 0; r < 4; r++)
        for (int j = t; j < HID; j += 128) {
            float v = Hm[(size_t)(b0 + r) * HID + j];
            hrow[r][j] = v;
            pr[r] += v * Wix[j];
        }
    for (int r = 0; r < 4; r++) red[r][t] = pr[r];
    __syncthreads();
    for (int s = 64; s > 0; s >>= 1) {
        if (t < s)
            for (int r = 0; r < 4; r++) red[r][t] += red[r][t + s];
        __syncthreads();
    }
    if (t < NOUT) {
        int o = t;
        float acc[4] = {0.f, 0.f, 0.f, 0.f};
        for (int u = 0; u < HID; u += 4) {
            float4 w4 = *(const float4*)&Wex[(size_t)o * HID + u];
            float wv[4] = {w4.x, w4.y, w4.z, w4.w};
            #pragma unroll
            for (int q = 0; q < 4; q++)
                #pragma unroll
                for (int r = 0; r < 4; r++)
                    acc[r] += hrow[r][u + q] * wv[q];
        }
        float wei = Wei[o], bo = bout[o];
        for (int r = 0; r < 4; r++)
            out[(size_t)(b0 + r) * NOUT + o] = acc[r] - red[r][0] * wei + bo;
    }
}

// ---------------------------------------------------------------------------
extern "C" void kernel_launch(void* const* d_in, const int* in_sizes, int n_in,
                              void* d_out, int out_size)
{
    const float* x      = (const float*)d_in[0];
    const float* ctx    = (const float*)d_in[1];
    const float* W1     = (const float*)d_in[2];
    const float* b1     = (const float*)d_in[3];
    const float* segW1  = (const float*)d_in[4];
    const float* maskW1 = (const float*)d_in[5];
    const float* maskS1 = (const float*)d_in[6];
    const float* W2     = (const float*)d_in[7];
    const float* b2     = (const float*)d_in[8];
    const float* segW2  = (const float*)d_in[9];
    const float* maskW2 = (const float*)d_in[10];
    const float* maskS2 = (const float*)d_in[11];
    const float* Wex    = (const float*)d_in[12];
    const float* Wix    = (const float*)d_in[13];
    const float* Wei    = (const float*)d_in[14];
    const float* bo     = (const float*)d_in[15];
    float* out = (float*)d_out;

    float *yb, *gb, *hb;
    cudaGetSymbolAddress((void**)&yb, g_y);
    cudaGetSymbolAddress((void**)&gb, g_gate);
    cudaGetSymbolAddress((void**)&hb, g_h);

    dim3 ffGrid(HID / 64, BB / 64);
    dim3 dendGrid(HID / 16, BB / 64);

    // Layer 1
    dend_kernel<<<dendGrid, 256>>>(ctx, segW1, maskS1, gb);
    ff_kernel<<<ffGrid, 256>>>(x, W1, maskW1, b1, yb, DIN);
    gate_topk_kernel<<<BB, 256>>>(yb, gb, hb);

    // Layer 2
    dend_kernel<<<dendGrid, 256>>>(ctx, segW2, maskS2, gb);
    ff_kernel<<<ffGrid, 256>>>(hb, W2, maskW2, b2, yb, HID);
    gate_topk_kernel<<<BB, 256>>>(yb, gb, hb);

    // Output head
    head_kernel<<<BB / 4, 128>>>(hb, Wex, Wix, Wei, bo, out);
}

// round 2
// speedup vs baseline: 1.5717x; 1.5717x over previous
#include <cuda_runtime.h>
#include <math.h>

#define BB    256
#define DIN   2048
#define HID   2048
#define NSEG  10
#define DCTX  1024
#define NOUT  100
#define TOPK  102

__device__ float g_y[BB * HID];
__device__ float g_gate[BB * HID];
__device__ float g_h[BB * HID];

// ---------------------------------------------------------------------------
// Dendrite + gating v2.
// d[b,u,s] = sum_c ctx[b,c]*segW[u,s,c]*maskS[u,s,c]
// gate[b,u] = sigmoid(d at argmax_s |d|)
// Tile: 128 batch x 16 units (x 10 segs). 256 threads.
// Thread microtile: 8 batch x 1 unit x 10 segs (80 FFMA per kk).
// smem: row-major, k-stride padded to 33 (33 = 1 mod 32 -> conflict-free).
// ---------------------------------------------------------------------------
#define D_KSTEP 32
#define D_MT    128
#define D_UT    16
#define D_ROWS  (D_UT * NSEG)   // 160

__global__ __launch_bounds__(256, 2) void dend_kernel(
    const float* __restrict__ ctx, const float* __restrict__ segW,
    const float* __restrict__ maskS, float* __restrict__ gate)
{
    __shared__ float Cs[D_MT][D_KSTEP + 1];     // [m][kk]  128x33
    __shared__ float Ws[D_ROWS][D_KSTEP + 1];   // [u*10+s][kk] 160x33

    int tid = threadIdx.x;
    int tx = tid & 15;          // unit within tile
    int ty = tid >> 4;          // batch group (8 rows each)
    int u0 = blockIdx.x * D_UT;
    int m0 = blockIdx.y * D_MT;

    float acc[8][10];
    #pragma unroll
    for (int i = 0; i < 8; i++)
        #pragma unroll
        for (int s = 0; s < 10; s++) acc[i][s] = 0.f;

    int lq = tid & 7;           // k-quad within row (float4)
    int lr = tid >> 3;          // row group

    for (int k0 = 0; k0 < DCTX; k0 += D_KSTEP) {
        // Load ctx tile: 128 rows x 32 k, float4 per task. 1024 tasks / 256 thr.
        #pragma unroll
        for (int it = 0; it < 4; it++) {
            int row = it * 32 + lr;   // 0..127
            float4 v = *(const float4*)&ctx[(size_t)(m0 + row) * DCTX + k0 + lq * 4];
            Cs[row][lq * 4 + 0] = v.x;
            Cs[row][lq * 4 + 1] = v.y;
            Cs[row][lq * 4 + 2] = v.z;
            Cs[row][lq * 4 + 3] = v.w;
        }
        // Load seg weights * mask: 160 rows x 32 k. 1280 tasks / 256 thr.
        #pragma unroll
        for (int it = 0; it < 5; it++) {
            int row = it * 32 + lr;   // 0..159 == (u*10+s), contiguous globally
            size_t off = ((size_t)u0 * NSEG + row) * DCTX + k0 + lq * 4;
            float4 w = *(const float4*)&segW[off];
            float4 m = *(const float4*)&maskS[off];
            Ws[row][lq * 4 + 0] = w.x * m.x;
            Ws[row][lq * 4 + 1] = w.y * m.y;
            Ws[row][lq * 4 + 2] = w.z * m.z;
            Ws[row][lq * 4 + 3] = w.w * m.w;
        }
        __syncthreads();

        #pragma unroll
        for (int kk = 0; kk < D_KSTEP; kk++) {
            float c[8], w[10];
            #pragma unroll
            for (int i = 0; i < 8; i++) c[i] = Cs[ty * 8 + i][kk];
            #pragma unroll
            for (int s = 0; s < 10; s++) w[s] = Ws[tx * 10 + s][kk];
            #pragma unroll
            for (int i = 0; i < 8; i++)
                #pragma unroll
                for (int s = 0; s < 10; s++)
                    acc[i][s] += c[i] * w[s];
        }
        __syncthreads();
    }

    #pragma unroll
    for (int i = 0; i < 8; i++) {
        float best = fabsf(acc[i][0]);
        float chosen = acc[i][0];
        #pragma unroll
        for (int s = 1; s < 10; s++) {
            float a = fabsf(acc[i][s]);
            if (a > best) { best = a; chosen = acc[i][s]; }
        }
        float gval = 1.f / (1.f + expf(-chosen));
        gate[(size_t)(m0 + ty * 8 + i) * HID + u0 + tx] = gval;
    }
}

// ---------------------------------------------------------------------------
// FF GEMM v2: Y[m,n] = sum_k X[m,k]*W[n,k]*Mk[n,k] + bias[n]
// Tile 64x64x32, 128 threads, 8x4 microtile. Pad-33 smem, coalesced loads.
// ---------------------------------------------------------------------------
#define F_KSTEP 32

__global__ __launch_bounds__(128) void ff_kernel(
    const float* __restrict__ X, const float* __restrict__ W,
    const float* __restrict__ Mk, const float* __restrict__ bias,
    float* __restrict__ Y, int K)
{
    __shared__ float As[64][F_KSTEP + 1];   // [m][kk]
    __shared__ float Bs[64][F_KSTEP + 1];   // [n][kk]

    int tid = threadIdx.x;
    int tx = tid & 15;      // n group (4 cols)
    int ty = tid >> 4;      // m group (8 rows)
    int n0 = blockIdx.x * 64, m0 = blockIdx.y * 64;

    float acc[8][4];
    #pragma unroll
    for (int i = 0; i < 8; i++)
        #pragma unroll
        for (int j = 0; j < 4; j++) acc[i][j] = 0.f;

    int lq = tid & 7;       // k-quad
    int lr = tid >> 3;      // row group (0..15)

    for (int k0 = 0; k0 < K; k0 += F_KSTEP) {
        #pragma unroll
        for (int it = 0; it < 4; it++) {
            int row = it * 16 + lr;   // 0..63
            float4 a = *(const float4*)&X[(size_t)(m0 + row) * K + k0 + lq * 4];
            As[row][lq * 4 + 0] = a.x;
            As[row][lq * 4 + 1] = a.y;
            As[row][lq * 4 + 2] = a.z;
            As[row][lq * 4 + 3] = a.w;
            size_t off = (size_t)(n0 + row) * K + k0 + lq * 4;
            float4 w = *(const float4*)&W[off];
            float4 m = *(const float4*)&Mk[off];
            Bs[row][lq * 4 + 0] = w.x * m.x;
            Bs[row][lq * 4 + 1] = w.y * m.y;
            Bs[row][lq * 4 + 2] = w.z * m.z;
            Bs[row][lq * 4 + 3] = w.w * m.w;
        }
        __syncthreads();

        #pragma unroll
        for (int kk = 0; kk < F_KSTEP; kk++) {
            float a[8], b[4];
            #pragma unroll
            for (int i = 0; i < 8; i++) a[i] = As[ty * 8 + i][kk];
            #pragma unroll
            for (int j = 0; j < 4; j++) b[j] = Bs[tx * 4 + j][kk];
            #pragma unroll
            for (int i = 0; i < 8; i++)
                #pragma unroll
                for (int j = 0; j < 4; j++)
                    acc[i][j] += a[i] * b[j];
        }
        __syncthreads();
    }

    #pragma unroll
    for (int i = 0; i < 8; i++) {
        int m = m0 + ty * 8 + i;
        #pragma unroll
        for (int j = 0; j < 4; j++) {
            int n = n0 + tx * 4 + j;
            Y[(size_t)m * HID + n] = acc[i][j] + bias[n];
        }
    }
}

// ---------------------------------------------------------------------------
// Gate multiply + k-winners (top 102 of 2048 per row). Radix-select with
// parallel suffix-scan digit selection.
// ---------------------------------------------------------------------------
__device__ __forceinline__ unsigned f2key(float f) {
    unsigned u = __float_as_uint(f);
    return (u & 0x80000000u) ? ~u : (u | 0x80000000u);
}

__global__ __launch_bounds__(256) void gate_topk_kernel(
    const float* __restrict__ Y, const float* __restrict__ G,
    float* __restrict__ H)
{
    __shared__ float    vals[HID];
    __shared__ unsigned keys[HID];
    __shared__ int      hist[256];
    __shared__ int      scan[2][256];
    __shared__ int      s_digit, s_rem, eqctr;
    int b = blockIdx.x;
    int t = threadIdx.x;
    const float* yr = Y + (size_t)b * HID;
    const float* gr = G + (size_t)b * HID;
    #pragma unroll
    for (int i = 0; i < HID / 256; i++) {
        int j = t + 256 * i;
        float v = yr[j] * gr[j];
        vals[j] = v;
        keys[j] = f2key(v);
    }
    __syncthreads();

    unsigned prefix = 0, pmask = 0;
    int remaining = TOPK;
    for (int pass = 0; pass < 4; pass++) {
        int shift = 24 - 8 * pass;
        hist[t] = 0;
        __syncthreads();
        #pragma unroll
        for (int i = 0; i < HID / 256; i++) {
            unsigned k = keys[t + 256 * i];
            if ((k & pmask) == prefix)
                atomicAdd(&hist[(k >> shift) & 255], 1);
        }
        __syncthreads();
        // inclusive suffix-sum over 256 bins (Hillis-Steele)
        scan[0][t] = hist[t];
        __syncthreads();
        int src = 0;
        #pragma unroll
        for (int s = 1; s < 256; s <<= 1) {
            int v = scan[src][t] + ((t + s < 256) ? scan[src][t + s] : 0);
            scan[src ^ 1][t] = v;
            src ^= 1;
            __syncthreads();
        }
        int sufT  = scan[src][t];
        int sufT1 = (t == 255) ? 0 : scan[src][t + 1];
        if (sufT >= remaining && sufT1 < remaining) {
            s_digit = t;
            s_rem = remaining - sufT1;
        }
        __syncthreads();
        prefix |= ((unsigned)s_digit) << shift;
        pmask  |= 0xFFu << shift;
        remaining = s_rem;
        __syncthreads();
    }

    if (t == 0) eqctr = 0;
    __syncthreads();
    unsigned T = prefix;
    int need = remaining;
    #pragma unroll
    for (int i = 0; i < HID / 256; i++) {
        int j = t + 256 * i;
        unsigned k = keys[j];
        float o = 0.f;
        if (k > T) o = vals[j];
        else if (k == T) {
            int slot = atomicAdd(&eqctr, 1);
            if (slot < need) o = vals[j];
        }
        H[(size_t)b * HID + j] = o;
    }
}

// ---------------------------------------------------------------------------
// Dale output head.
// ---------------------------------------------------------------------------
__global__ __launch_bounds__(128) void head_kernel(
    const float* __restrict__ Hm, const float* __restrict__ Wex,
    const float* __restrict__ Wix, const float* __restrict__ Wei,
    const float* __restrict__ bout, float* __restrict__ out)
{
    __shared__ float hrow[4][HID];
    __shared__ float red[4][128];
    int b0 = blockIdx.x * 4;
    int t = threadIdx.x;
    float pr[4] = {0.f, 0.f, 0.f, 0.f};
    for (int r = 0; r < 4; r++)
        for (int j = t; j < HID; j += 128) {
            float v = Hm[(size_t)(b0 + r) * HID + j];
            hrow[r][j] = v;
            pr[r] += v * Wix[j];
        }
    for (int r = 0; r < 4; r++) red[r][t] = pr[r];
    __syncthreads();
    for (int s = 64; s > 0; s >>= 1) {
        if (t < s)
            for (int r = 0; r < 4; r++) red[r][t] += red[r][t + s];
        __syncthreads();
    }
    if (t < NOUT) {
        int o = t;
        float acc[4] = {0.f, 0.f, 0.f, 0.f};
        for (int u = 0; u < HID; u += 4) {
            float4 w4 = *(const float4*)&Wex[(size_t)o * HID + u];
            float wv[4] = {w4.x, w4.y, w4.z, w4.w};
            #pragma unroll
            for (int q = 0; q < 4; q++)
                #pragma unroll
                for (int r = 0; r < 4; r++)
                    acc[r] += hrow[r][u + q] * wv[q];
        }
        float wei = Wei[o], bo = bout[o];
        for (int r = 0; r < 4; r++)
            out[(size_t)(b0 + r) * NOUT + o] = acc[r] - red[r][0] * wei + bo;
    }
}

// ---------------------------------------------------------------------------
extern "C" void kernel_launch(void* const* d_in, const int* in_sizes, int n_in,
                              void* d_out, int out_size)
{
    const float* x      = (const float*)d_in[0];
    const float* ctx    = (const float*)d_in[1];
    const float* W1     = (const float*)d_in[2];
    const float* b1     = (const float*)d_in[3];
    const float* segW1  = (const float*)d_in[4];
    const float* maskW1 = (const float*)d_in[5];
    const float* maskS1 = (const float*)d_in[6];
    const float* W2     = (const float*)d_in[7];
    const float* b2     = (const float*)d_in[8];
    const float* segW2  = (const float*)d_in[9];
    const float* maskW2 = (const float*)d_in[10];
    const float* maskS2 = (const float*)d_in[11];
    const float* Wex    = (const float*)d_in[12];
    const float* Wix    = (const float*)d_in[13];
    const float* Wei    = (const float*)d_in[14];
    const float* bo     = (const float*)d_in[15];
    float* out = (float*)d_out;

    float *yb, *gb, *hb;
    cudaGetSymbolAddress((void**)&yb, g_y);
    cudaGetSymbolAddress((void**)&gb, g_gate);
    cudaGetSymbolAddress((void**)&hb, g_h);

    dim3 ffGrid(HID / 64, BB / 64);
    dim3 dendGrid(HID / D_UT, BB / D_MT);

    // Layer 1
    dend_kernel<<<dendGrid, 256>>>(ctx, segW1, maskS1, gb);
    ff_kernel<<<ffGrid, 128>>>(x, W1, maskW1, b1, yb, DIN);
    gate_topk_kernel<<<BB, 256>>>(yb, gb, hb);

    // Layer 2
    dend_kernel<<<dendGrid, 256>>>(ctx, segW2, maskS2, gb);
    ff_kernel<<<ffGrid, 128>>>(hb, W2, maskW2, b2, yb, HID);
    gate_topk_kernel<<<BB, 256>>>(yb, gb, hb);

    // Output head
    head_kernel<<<BB / 4, 128>>>(hb, Wex, Wix, Wei, bo, out);
}